// round 16
// baseline (speedup 1.0000x reference)
#include <cuda_runtime.h>
#include <math.h>

#define L_LAYERS 4
#define D_MODEL  2304
#define F_FF     9216
#define N_HEADS  8
#define K_HEADS  4
#define H_DIM    256
#define BATCH    2
#define SEQ      2048
#define ROWS     (BATCH*SEQ)
#define VOCAB    32000
#define QCOLS    (N_HEADS*H_DIM)
#define KVCOLS   (K_HEADS*H_DIM)

// ---------------- device scratch ----------------
__device__ float g_x   [ROWS*D_MODEL];
__device__ float g_h   [ROWS*D_MODEL];
__device__ float g_tmpD[ROWS*D_MODEL];
__device__ float g_q   [ROWS*QCOLS];
__device__ float g_att [ROWS*QCOLS];
__device__ float g_k   [ROWS*KVCOLS];
__device__ float g_v   [ROWS*KVCOLS];
__device__ float g_gate[(size_t)ROWS*F_FF];
__device__ float g_up  [(size_t)ROWS*F_FF];
__device__ float g_wq  [(size_t)L_LAYERS*D_MODEL*QCOLS];
__device__ float g_wkv [(size_t)L_LAYERS*2*D_MODEL*KVCOLS];
__device__ float g_embT[(size_t)D_MODEL*VOCAB];
__device__ float g_sin [2*SEQ*128];
__device__ float g_cos [2*SEQ*128];

// ---------------- rope tables ----------------
__global__ void rope_table_kernel(float* __restrict__ sint, float* __restrict__ cost) {
    int t = blockIdx.x, sel = blockIdx.y, i = threadIdx.x;
    double base  = sel ? 1000000.0 : 10000.0;
    double scale = sel ? 8.0 : 1.0;
    double fr = (2.0 * (double)i) / 256.0;
    double ang = ((double)t / scale) / pow(base, fr);
    sint[((size_t)sel*SEQ + t)*128 + i] = (float)sin(ang);
    cost[((size_t)sel*SEQ + t)*128 + i] = (float)cos(ang);
}

// ---------------- weight repacks ----------------
__global__ void repack_wq_kernel(const float* __restrict__ w, float* __restrict__ o) {
    size_t idx = (size_t)blockIdx.x * blockDim.x + threadIdx.x;
    size_t tot = (size_t)L_LAYERS * D_MODEL * QCOLS;
    if (idx >= tot) return;
    int c = (int)(idx % QCOLS);
    size_t r = idx / QCOLS;
    int d = (int)(r % D_MODEL);
    int l = (int)(r / D_MODEL);
    int n = c >> 8, hh = c & 255;
    o[idx] = w[(((size_t)l*N_HEADS + n)*D_MODEL + d)*H_DIM + hh];
}
__global__ void repack_wkv_kernel(const float* __restrict__ w, float* __restrict__ o) {
    size_t idx = (size_t)blockIdx.x * blockDim.x + threadIdx.x;
    size_t tot = (size_t)L_LAYERS * 2 * D_MODEL * KVCOLS;
    if (idx >= tot) return;
    int c = (int)(idx % KVCOLS);
    size_t r = idx / KVCOLS;
    int d = (int)(r % D_MODEL);
    size_t r2 = r / D_MODEL;
    int s = (int)(r2 % 2);
    int l = (int)(r2 / 2);
    int k = c >> 8, hh = c & 255;
    o[idx] = w[((((size_t)l*2 + s)*K_HEADS + k)*D_MODEL + d)*H_DIM + hh];
}
// transpose in[R,C] -> out[C,R]
__global__ void transpose_kernel(const float* __restrict__ in, float* __restrict__ out,
                                 int R, int C) {
    __shared__ float tile[32][33];
    int c0 = blockIdx.x*32, r0 = blockIdx.y*32;
    int x = threadIdx.x, y = threadIdx.y;
    #pragma unroll
    for (int dy = 0; dy < 32; dy += 8)
        tile[y+dy][x] = in[(size_t)(r0+y+dy)*C + c0+x];
    __syncthreads();
    #pragma unroll
    for (int dy = 0; dy < 32; dy += 8)
        out[(size_t)(c0+y+dy)*R + r0+x] = tile[x][y+dy];
}

// ---------------- embedding gather ----------------
__global__ void embed_kernel(const int* __restrict__ tokens, const float* __restrict__ embed,
                             float* __restrict__ out) {
    int r = blockIdx.x;
    int tok = tokens[r];
    const float4* src = (const float4*)(embed + (size_t)tok * D_MODEL);
    float4* dst = (float4*)(out + (size_t)r * D_MODEL);
    for (int i = threadIdx.x; i < D_MODEL/4; i += blockDim.x) {
        float4 v = src[i];
        v.x *= 48.0f; v.y *= 48.0f; v.z *= 48.0f; v.w *= 48.0f;
        dst[i] = v;
    }
}

__device__ __forceinline__ float block_sum_256(float v) {
    __shared__ float sh[8];
    int lane = threadIdx.x & 31, w = threadIdx.x >> 5;
    #pragma unroll
    for (int o = 16; o; o >>= 1) v += __shfl_xor_sync(0xffffffffu, v, o);
    if (lane == 0) sh[w] = v;
    __syncthreads();
    float r = 0.f;
    #pragma unroll
    for (int k = 0; k < 8; k++) r += sh[k];
    __syncthreads();
    return r;
}

__global__ void rmsnorm_kernel(const float* __restrict__ in, const float* __restrict__ g,
                               float* __restrict__ out, int dim) {
    size_t base = (size_t)blockIdx.x * dim;
    const float4* x4 = (const float4*)(in + base);
    float4* o4 = (float4*)(out + base);
    const float4* g4 = (const float4*)g;
    int n4 = dim >> 2;
    float ss = 0.f;
    for (int i = threadIdx.x; i < n4; i += 256) {
        float4 v = x4[i];
        ss += v.x*v.x + v.y*v.y + v.z*v.z + v.w*v.w;
    }
    ss = block_sum_256(ss);
    float rs = rsqrtf(ss / (float)dim + 1e-6f);
    for (int i = threadIdx.x; i < n4; i += 256) {
        float4 v = x4[i], gg = g4[i];
        v.x *= rs * (1.f + gg.x); v.y *= rs * (1.f + gg.y);
        v.z *= rs * (1.f + gg.z); v.w *= rs * (1.f + gg.w);
        o4[i] = v;
    }
}

__global__ void add_rmsnorm_kernel(const float* __restrict__ in, const float* __restrict__ g,
                                   float* __restrict__ x, int dim) {
    size_t base = (size_t)blockIdx.x * dim;
    const float4* i4 = (const float4*)(in + base);
    float4* x4 = (float4*)(x + base);
    const float4* g4 = (const float4*)g;
    int n4 = dim >> 2;
    float ss = 0.f;
    for (int i = threadIdx.x; i < n4; i += 256) {
        float4 v = i4[i];
        ss += v.x*v.x + v.y*v.y + v.z*v.z + v.w*v.w;
    }
    ss = block_sum_256(ss);
    float rs = rsqrtf(ss / (float)dim + 1e-6f);
    for (int i = threadIdx.x; i < n4; i += 256) {
        float4 v = i4[i], gg = g4[i], xx = x4[i];
        xx.x += v.x * rs * (1.f + gg.x);
        xx.y += v.y * rs * (1.f + gg.y);
        xx.z += v.z * rs * (1.f + gg.z);
        xx.w += v.w * rs * (1.f + gg.w);
        x4[i] = xx;
    }
}

// per-head QK-norm + RoPE (+ query scale); 128 threads, grid(ROWS, nheads)
__global__ void qk_rope_kernel(float* __restrict__ buf, int nheads,
                               const float* __restrict__ norm,
                               const float* __restrict__ sint,
                               const float* __restrict__ cost,
                               float outscale) {
    int r = blockIdx.x, head = blockIdx.y;
    int t = r & (SEQ - 1);
    float* p = buf + ((size_t)r * nheads + head) * H_DIM;
    int i = threadIdx.x;
    float v1 = p[i], v2 = p[i + 128];
    float ss = v1*v1 + v2*v2;
    #pragma unroll
    for (int o = 16; o; o >>= 1) ss += __shfl_xor_sync(0xffffffffu, ss, o);
    __shared__ float sh[4];
    int lane = i & 31, w = i >> 5;
    if (lane == 0) sh[w] = ss;
    __syncthreads();
    ss = sh[0] + sh[1] + sh[2] + sh[3];
    float rs = rsqrtf(ss * (1.f/256.f) + 1e-6f);
    float n1 = v1 * rs * (1.f + norm[i]);
    float n2 = v2 * rs * (1.f + norm[i + 128]);
    float sn = sint[t*128 + i], cs = cost[t*128 + i];
    p[i]       = (n1 * cs - n2 * sn) * outscale;
    p[i + 128] = (n2 * cs + n1 * sn) * outscale;
}

__global__ void geglu_kernel(float* __restrict__ gate, const float* __restrict__ up, size_t n) {
    size_t i = (size_t)blockIdx.x * blockDim.x + threadIdx.x;
    if (i < n) {
        float x = gate[i];
        float t = tanhf(0.7978845608028654f * (x + 0.044715f * x * x * x));
        gate[i] = 0.5f * x * (1.f + t) * up[i];
    }
}

// ---------------- SGEMM NN: C[M,N] = A[M,K] @ B[K,N], all %128 / %8 ----------------
__global__ __launch_bounds__(256) void sgemm_nn(
    const float* __restrict__ A, const float* __restrict__ B, float* __restrict__ C,
    int M, int N, int K, int mode) {
    __shared__ float As[8][128];
    __shared__ float Bs[8][128];
    int tid = threadIdx.x;
    int bm = blockIdx.y * 128, bn = blockIdx.x * 128;
    int arow = tid >> 1,  acol = (tid & 1) * 4;
    int brow = tid >> 5,  bcol = (tid & 31) * 4;
    int ty = tid >> 4,    tx = tid & 15;
    float acc[8][8];
    #pragma unroll
    for (int i = 0; i < 8; i++)
        #pragma unroll
        for (int j = 0; j < 8; j++) acc[i][j] = 0.f;
    const float* Ap = A + (size_t)(bm + arow) * K + acol;
    const float* Bp = B + (size_t)brow * N + bn + bcol;
    for (int k0 = 0; k0 < K; k0 += 8) {
        float4 av = *(const float4*)(Ap + k0);
        As[acol+0][arow] = av.x; As[acol+1][arow] = av.y;
        As[acol+2][arow] = av.z; As[acol+3][arow] = av.w;
        *(float4*)(&Bs[brow][bcol]) = *(const float4*)(Bp + (size_t)k0 * N);
        __syncthreads();
        #pragma unroll
        for (int kk = 0; kk < 8; kk++) {
            float a[8], b[8];
            *(float4*)(&a[0]) = *(const float4*)(&As[kk][ty*4]);
            *(float4*)(&a[4]) = *(const float4*)(&As[kk][64 + ty*4]);
            *(float4*)(&b[0]) = *(const float4*)(&Bs[kk][tx*4]);
            *(float4*)(&b[4]) = *(const float4*)(&Bs[kk][64 + tx*4]);
            #pragma unroll
            for (int i = 0; i < 8; i++)
                #pragma unroll
                for (int j = 0; j < 8; j++) acc[i][j] += a[i] * b[j];
        }
        __syncthreads();
    }
    #pragma unroll
    for (int i = 0; i < 8; i++) {
        int row = bm + (i < 4 ? ty*4 + i : 64 + ty*4 + (i-4));
        float* Cr = C + (size_t)row * N + bn;
        float4 v0, v1;
        v0.x = acc[i][0]; v0.y = acc[i][1]; v0.z = acc[i][2]; v0.w = acc[i][3];
        v1.x = acc[i][4]; v1.y = acc[i][5]; v1.z = acc[i][6]; v1.w = acc[i][7];
        if (mode == 1) {
            v0.x = 30.f*tanhf(v0.x/30.f); v0.y = 30.f*tanhf(v0.y/30.f);
            v0.z = 30.f*tanhf(v0.z/30.f); v0.w = 30.f*tanhf(v0.w/30.f);
            v1.x = 30.f*tanhf(v1.x/30.f); v1.y = 30.f*tanhf(v1.y/30.f);
            v1.z = 30.f*tanhf(v1.z/30.f); v1.w = 30.f*tanhf(v1.w/30.f);
        }
        *(float4*)(Cr + tx*4)      = v0;
        *(float4*)(Cr + 64 + tx*4) = v1;
    }
}

// ---------------- attention (no-shift softmax: tanh-cap bounds logits) ----------------
#define QSTR 260
#define ATTN_SMEM_FLOATS (64*QSTR*2 + 64*65 + 64)
__global__ __launch_bounds__(256) void attn_kernel(
    const float* __restrict__ q, const float* __restrict__ k, const float* __restrict__ v,
    float* __restrict__ o, int is_local) {
    extern __shared__ float sm[];
    float* Qs  = sm;
    float* Ks  = Qs + 64*QSTR;
    float* Ps  = Ks + 64*QSTR;
    float* den = Ps + 64*65;
    int tid = threadIdx.x;
    int ty = tid >> 4, tx = tid & 15;
    int t0 = blockIdx.x * 64;
    int n = blockIdx.y, b = blockIdx.z;
    int kvh = n >> 1;

    for (int idx = tid; idx < 64*64; idx += 256) {   // float4 units
        int row = idx >> 6, c4 = idx & 63;
        *(float4*)(&Qs[row*QSTR + c4*4]) =
            *(const float4*)(q + ((size_t)((b*SEQ + t0 + row)*N_HEADS + n))*H_DIM + c4*4);
    }
    if (tid < 64) den[tid] = 0.f;
    float acc[4][16];
    #pragma unroll
    for (int i = 0; i < 4; i++)
        #pragma unroll
        for (int j = 0; j < 16; j++) acc[i][j] = 0.f;

    int s_lo = 0;
    if (is_local) { int lo = t0 - 1023; if (lo > 0) s_lo = lo & ~63; }
    for (int s0 = s_lo; s0 <= t0 + 63; s0 += 64) {
        for (int idx = tid; idx < 64*64; idx += 256) {
            int row = idx >> 6, c4 = idx & 63;
            *(float4*)(&Ks[row*QSTR + c4*4]) =
                *(const float4*)(k + ((size_t)((b*SEQ + s0 + row)*K_HEADS + kvh))*H_DIM + c4*4);
        }
        __syncthreads();
        float s[4][4];
        #pragma unroll
        for (int i = 0; i < 4; i++)
            #pragma unroll
            for (int j = 0; j < 4; j++) s[i][j] = 0.f;
        for (int kk = 0; kk < H_DIM; kk += 4) {
            float4 a[4], bb[4];
            #pragma unroll
            for (int i = 0; i < 4; i++) a[i]  = *(const float4*)(&Qs[(ty*4+i)*QSTR + kk]);
            #pragma unroll
            for (int j = 0; j < 4; j++) bb[j] = *(const float4*)(&Ks[(tx*4+j)*QSTR + kk]);
            #pragma unroll
            for (int i = 0; i < 4; i++)
                #pragma unroll
                for (int j = 0; j < 4; j++)
                    s[i][j] += a[i].x*bb[j].x + a[i].y*bb[j].y + a[i].z*bb[j].z + a[i].w*bb[j].w;
        }
        #pragma unroll
        for (int i = 0; i < 4; i++) {
            int t = t0 + ty*4 + i;
            #pragma unroll
            for (int j = 0; j < 4; j++) {
                int ss = s0 + tx*4 + j;
                float l = 50.f * tanhf(s[i][j] * 0.02f);
                bool ok = (ss <= t) && (!is_local || (t - ss) < 1024);
                Ps[(ty*4+i)*65 + tx*4 + j] = ok ? expf(l) : 0.f;
            }
        }
        __syncthreads();
        if (tid < 64) {
            float d = 0.f;
            #pragma unroll 8
            for (int ss = 0; ss < 64; ss++) d += Ps[tid*65 + ss];
            den[tid] += d;
        }
        for (int idx = tid; idx < 64*64; idx += 256) {
            int row = idx >> 6, c4 = idx & 63;
            *(float4*)(&Ks[row*QSTR + c4*4]) =
                *(const float4*)(v + ((size_t)((b*SEQ + s0 + row)*K_HEADS + kvh))*H_DIM + c4*4);
        }
        __syncthreads();
        for (int ss = 0; ss < 64; ss++) {
            float pr[4];
            #pragma unroll
            for (int i = 0; i < 4; i++) pr[i] = Ps[(ty*4+i)*65 + ss];
            #pragma unroll
            for (int j = 0; j < 16; j++) {
                float vv = Ks[ss*QSTR + j*16 + tx];
                #pragma unroll
                for (int i = 0; i < 4; i++) acc[i][j] += pr[i] * vv;
            }
        }
        __syncthreads();
    }
    #pragma unroll
    for (int i = 0; i < 4; i++) {
        int row = ty*4 + i;
        float inv = 1.f / den[row];
        float* op = o + ((size_t)((b*SEQ + t0 + row)*N_HEADS + n))*H_DIM;
        #pragma unroll
        for (int j = 0; j < 16; j++) op[j*16 + tx] = acc[i][j] * inv;
    }
}

// ---------------- host ----------------
static void* sym(const void* s) { void* p = nullptr; cudaGetSymbolAddress(&p, s); return p; }

extern "C" void kernel_launch(void* const* d_in, const int* in_sizes, int n_in,
                              void* d_out, int out_size) {
    const int*   tokens        = (const int*)  d_in[0];
    const float* embed         = (const float*)d_in[1];
    const float* w_q           = (const float*)d_in[2];
    const float* w_kv          = (const float*)d_in[3];
    const float* w_o           = (const float*)d_in[4];
    const float* attn_norm     = (const float*)d_in[5];
    const float* post_attn     = (const float*)d_in[6];
    const float* ffw_norm      = (const float*)d_in[7];
    const float* post_ffw      = (const float*)d_in[8];
    const float* q_norm        = (const float*)d_in[9];
    const float* k_norm        = (const float*)d_in[10];
    const float* gate_w        = (const float*)d_in[11];
    const float* down_w        = (const float*)d_in[12];
    const float* final_norm    = (const float*)d_in[13];
    float* out = (float*)d_out;

    float* x    = (float*)sym(g_x);
    float* h    = (float*)sym(g_h);
    float* tmpD = (float*)sym(g_tmpD);
    float* qb   = (float*)sym(g_q);
    float* att  = (float*)sym(g_att);
    float* kb   = (float*)sym(g_k);
    float* vb   = (float*)sym(g_v);
    float* gate = (float*)sym(g_gate);
    float* up   = (float*)sym(g_up);
    float* wq   = (float*)sym(g_wq);
    float* wkv  = (float*)sym(g_wkv);
    float* embT = (float*)sym(g_embT);
    float* sint = (float*)sym(g_sin);
    float* cost = (float*)sym(g_cos);

    cudaFuncSetAttribute(attn_kernel, cudaFuncAttributeMaxDynamicSharedMemorySize,
                         ATTN_SMEM_FLOATS * 4);

    // setup
    rope_table_kernel<<<dim3(SEQ, 2), 128>>>(sint, cost);
    {
        size_t tot = (size_t)L_LAYERS * D_MODEL * QCOLS;
        repack_wq_kernel<<<(unsigned)((tot + 255) / 256), 256>>>(w_q, wq);
        tot = (size_t)L_LAYERS * 2 * D_MODEL * KVCOLS;
        repack_wkv_kernel<<<(unsigned)((tot + 255) / 256), 256>>>(w_kv, wkv);
    }
    transpose_kernel<<<dim3(D_MODEL/32, VOCAB/32), dim3(32, 8)>>>(embed, embT, VOCAB, D_MODEL);
    embed_kernel<<<ROWS, 256>>>(tokens, embed, x);

    for (int l = 0; l < L_LAYERS; l++) {
        int is_local = (l % 2 == 0);
        const float* stab = sint + (size_t)(is_local ? 0 : 1) * SEQ * 128;
        const float* ctab = cost + (size_t)(is_local ? 0 : 1) * SEQ * 128;
        // attention block
        rmsnorm_kernel<<<ROWS, 256>>>(x, attn_norm + (size_t)l*D_MODEL, h, D_MODEL);
        sgemm_nn<<<dim3(QCOLS/128,  ROWS/128), 256>>>(h, wq  + (size_t)l*D_MODEL*QCOLS, qb,
                                                      ROWS, QCOLS, D_MODEL, 0);
        sgemm_nn<<<dim3(KVCOLS/128, ROWS/128), 256>>>(h, wkv + (size_t)(l*2+0)*D_MODEL*KVCOLS, kb,
                                                      ROWS, KVCOLS, D_MODEL, 0);
        sgemm_nn<<<dim3(KVCOLS/128, ROWS/128), 256>>>(h, wkv + (size_t)(l*2+1)*D_MODEL*KVCOLS, vb,
                                                      ROWS, KVCOLS, D_MODEL, 0);
        qk_rope_kernel<<<dim3(ROWS, N_HEADS), 128>>>(qb, N_HEADS, q_norm + (size_t)l*H_DIM,
                                                     stab, ctab, 0.0625f);
        qk_rope_kernel<<<dim3(ROWS, K_HEADS), 128>>>(kb, K_HEADS, k_norm + (size_t)l*H_DIM,
                                                     stab, ctab, 1.0f);
        attn_kernel<<<dim3(SEQ/64, N_HEADS, BATCH), 256, ATTN_SMEM_FLOATS*4>>>(
            qb, kb, vb, att, is_local);
        sgemm_nn<<<dim3(D_MODEL/128, ROWS/128), 256>>>(att, w_o + (size_t)l*QCOLS*D_MODEL, tmpD,
                                                       ROWS, D_MODEL, QCOLS, 0);
        add_rmsnorm_kernel<<<ROWS, 256>>>(tmpD, post_attn + (size_t)l*D_MODEL, x, D_MODEL);
        // MLP block
        rmsnorm_kernel<<<ROWS, 256>>>(x, ffw_norm + (size_t)l*D_MODEL, h, D_MODEL);
        sgemm_nn<<<dim3(F_FF/128, ROWS/128), 256>>>(h, gate_w + (size_t)(l*2+0)*D_MODEL*F_FF, gate,
                                                    ROWS, F_FF, D_MODEL, 0);
        sgemm_nn<<<dim3(F_FF/128, ROWS/128), 256>>>(h, gate_w + (size_t)(l*2+1)*D_MODEL*F_FF, up,
                                                    ROWS, F_FF, D_MODEL, 0);
        {
            size_t n = (size_t)ROWS * F_FF;
            geglu_kernel<<<(unsigned)((n + 255) / 256), 256>>>(gate, up, n);
        }
        sgemm_nn<<<dim3(D_MODEL/128, ROWS/128), 256>>>(gate, down_w + (size_t)l*F_FF*D_MODEL, tmpD,
                                                       ROWS, D_MODEL, F_FF, 0);
        add_rmsnorm_kernel<<<ROWS, 256>>>(tmpD, post_ffw + (size_t)l*D_MODEL, x, D_MODEL);
    }
    // final norm + tied decode with tanh cap
    rmsnorm_kernel<<<ROWS, 256>>>(x, final_norm, h, D_MODEL);
    sgemm_nn<<<dim3(VOCAB/128, ROWS/128), 256>>>(h, embT, out, ROWS, VOCAB, D_MODEL, 1);
}

// round 17
// speedup vs baseline: 1.0007x; 1.0007x over previous
#include <cuda_runtime.h>
#include <math.h>

#define L_LAYERS 4
#define D_MODEL  2304
#define F_FF     9216
#define N_HEADS  8
#define K_HEADS  4
#define H_DIM    256
#define BATCH    2
#define SEQ      2048
#define ROWS     (BATCH*SEQ)
#define VOCAB    32000
#define QCOLS    (N_HEADS*H_DIM)
#define KVCOLS   (K_HEADS*H_DIM)

// ---------------- device scratch ----------------
__device__ float g_x   [ROWS*D_MODEL];
__device__ float g_h   [ROWS*D_MODEL];
__device__ float g_tmpD[ROWS*D_MODEL];
__device__ float g_q   [ROWS*QCOLS];
__device__ float g_att [ROWS*QCOLS];
__device__ float g_k   [ROWS*KVCOLS];
__device__ float g_v   [ROWS*KVCOLS];
__device__ float g_gate[(size_t)ROWS*F_FF];
__device__ float g_up  [(size_t)ROWS*F_FF];
__device__ float g_wq  [(size_t)L_LAYERS*D_MODEL*QCOLS];
__device__ float g_wkv [(size_t)L_LAYERS*2*D_MODEL*KVCOLS];
__device__ float g_embT[(size_t)D_MODEL*VOCAB];
__device__ float g_sin [2*SEQ*128];
__device__ float g_cos [2*SEQ*128];

// ---------------- rope tables ----------------
__global__ void rope_table_kernel(float* __restrict__ sint, float* __restrict__ cost) {
    int t = blockIdx.x, sel = blockIdx.y, i = threadIdx.x;
    double base  = sel ? 1000000.0 : 10000.0;
    double scale = sel ? 8.0 : 1.0;
    double fr = (2.0 * (double)i) / 256.0;
    double ang = ((double)t / scale) / pow(base, fr);
    sint[((size_t)sel*SEQ + t)*128 + i] = (float)sin(ang);
    cost[((size_t)sel*SEQ + t)*128 + i] = (float)cos(ang);
}

// ---------------- weight repacks ----------------
__global__ void repack_wq_kernel(const float* __restrict__ w, float* __restrict__ o) {
    size_t idx = (size_t)blockIdx.x * blockDim.x + threadIdx.x;
    size_t tot = (size_t)L_LAYERS * D_MODEL * QCOLS;
    if (idx >= tot) return;
    int c = (int)(idx % QCOLS);
    size_t r = idx / QCOLS;
    int d = (int)(r % D_MODEL);
    int l = (int)(r / D_MODEL);
    int n = c >> 8, hh = c & 255;
    o[idx] = w[(((size_t)l*N_HEADS + n)*D_MODEL + d)*H_DIM + hh];
}
__global__ void repack_wkv_kernel(const float* __restrict__ w, float* __restrict__ o) {
    size_t idx = (size_t)blockIdx.x * blockDim.x + threadIdx.x;
    size_t tot = (size_t)L_LAYERS * 2 * D_MODEL * KVCOLS;
    if (idx >= tot) return;
    int c = (int)(idx % KVCOLS);
    size_t r = idx / KVCOLS;
    int d = (int)(r % D_MODEL);
    size_t r2 = r / D_MODEL;
    int s = (int)(r2 % 2);
    int l = (int)(r2 / 2);
    int k = c >> 8, hh = c & 255;
    o[idx] = w[((((size_t)l*2 + s)*K_HEADS + k)*D_MODEL + d)*H_DIM + hh];
}
// transpose in[R,C] -> out[C,R]
__global__ void transpose_kernel(const float* __restrict__ in, float* __restrict__ out,
                                 int R, int C) {
    __shared__ float tile[32][33];
    int c0 = blockIdx.x*32, r0 = blockIdx.y*32;
    int x = threadIdx.x, y = threadIdx.y;
    #pragma unroll
    for (int dy = 0; dy < 32; dy += 8)
        tile[y+dy][x] = in[(size_t)(r0+y+dy)*C + c0+x];
    __syncthreads();
    #pragma unroll
    for (int dy = 0; dy < 32; dy += 8)
        out[(size_t)(c0+y+dy)*R + r0+x] = tile[x][y+dy];
}

// ---------------- embedding gather ----------------
__global__ void embed_kernel(const int* __restrict__ tokens, const float* __restrict__ embed,
                             float* __restrict__ out) {
    int r = blockIdx.x;
    int tok = tokens[r];
    const float4* src = (const float4*)(embed + (size_t)tok * D_MODEL);
    float4* dst = (float4*)(out + (size_t)r * D_MODEL);
    for (int i = threadIdx.x; i < D_MODEL/4; i += blockDim.x) {
        float4 v = src[i];
        v.x *= 48.0f; v.y *= 48.0f; v.z *= 48.0f; v.w *= 48.0f;
        dst[i] = v;
    }
}

__device__ __forceinline__ float block_sum_256(float v) {
    __shared__ float sh[8];
    int lane = threadIdx.x & 31, w = threadIdx.x >> 5;
    #pragma unroll
    for (int o = 16; o; o >>= 1) v += __shfl_xor_sync(0xffffffffu, v, o);
    if (lane == 0) sh[w] = v;
    __syncthreads();
    float r = 0.f;
    #pragma unroll
    for (int k = 0; k < 8; k++) r += sh[k];
    __syncthreads();
    return r;
}

__global__ void rmsnorm_kernel(const float* __restrict__ in, const float* __restrict__ g,
                               float* __restrict__ out, int dim) {
    size_t base = (size_t)blockIdx.x * dim;
    const float4* x4 = (const float4*)(in + base);
    float4* o4 = (float4*)(out + base);
    const float4* g4 = (const float4*)g;
    int n4 = dim >> 2;
    float ss = 0.f;
    for (int i = threadIdx.x; i < n4; i += 256) {
        float4 v = x4[i];
        ss += v.x*v.x + v.y*v.y + v.z*v.z + v.w*v.w;
    }
    ss = block_sum_256(ss);
    float rs = rsqrtf(ss / (float)dim + 1e-6f);
    for (int i = threadIdx.x; i < n4; i += 256) {
        float4 v = x4[i], gg = g4[i];
        v.x *= rs * (1.f + gg.x); v.y *= rs * (1.f + gg.y);
        v.z *= rs * (1.f + gg.z); v.w *= rs * (1.f + gg.w);
        o4[i] = v;
    }
}

__global__ void add_rmsnorm_kernel(const float* __restrict__ in, const float* __restrict__ g,
                                   float* __restrict__ x, int dim) {
    size_t base = (size_t)blockIdx.x * dim;
    const float4* i4 = (const float4*)(in + base);
    float4* x4 = (float4*)(x + base);
    const float4* g4 = (const float4*)g;
    int n4 = dim >> 2;
    float ss = 0.f;
    for (int i = threadIdx.x; i < n4; i += 256) {
        float4 v = i4[i];
        ss += v.x*v.x + v.y*v.y + v.z*v.z + v.w*v.w;
    }
    ss = block_sum_256(ss);
    float rs = rsqrtf(ss / (float)dim + 1e-6f);
    for (int i = threadIdx.x; i < n4; i += 256) {
        float4 v = i4[i], gg = g4[i], xx = x4[i];
        xx.x += v.x * rs * (1.f + gg.x);
        xx.y += v.y * rs * (1.f + gg.y);
        xx.z += v.z * rs * (1.f + gg.z);
        xx.w += v.w * rs * (1.f + gg.w);
        x4[i] = xx;
    }
}

// per-head QK-norm + RoPE (+ query scale); 128 threads, grid(ROWS, nheads)
__global__ void qk_rope_kernel(float* __restrict__ buf, int nheads,
                               const float* __restrict__ norm,
                               const float* __restrict__ sint,
                               const float* __restrict__ cost,
                               float outscale) {
    int r = blockIdx.x, head = blockIdx.y;
    int t = r & (SEQ - 1);
    float* p = buf + ((size_t)r * nheads + head) * H_DIM;
    int i = threadIdx.x;
    float v1 = p[i], v2 = p[i + 128];
    float ss = v1*v1 + v2*v2;
    #pragma unroll
    for (int o = 16; o; o >>= 1) ss += __shfl_xor_sync(0xffffffffu, ss, o);
    __shared__ float sh[4];
    int lane = i & 31, w = i >> 5;
    if (lane == 0) sh[w] = ss;
    __syncthreads();
    ss = sh[0] + sh[1] + sh[2] + sh[3];
    float rs = rsqrtf(ss * (1.f/256.f) + 1e-6f);
    float n1 = v1 * rs * (1.f + norm[i]);
    float n2 = v2 * rs * (1.f + norm[i + 128]);
    float sn = sint[t*128 + i], cs = cost[t*128 + i];
    p[i]       = (n1 * cs - n2 * sn) * outscale;
    p[i + 128] = (n2 * cs + n1 * sn) * outscale;
}

__global__ void geglu_kernel(float* __restrict__ gate, const float* __restrict__ up, size_t n) {
    size_t i = (size_t)blockIdx.x * blockDim.x + threadIdx.x;
    if (i < n) {
        float x = gate[i];
        float t = tanhf(0.7978845608028654f * (x + 0.044715f * x * x * x));
        gate[i] = 0.5f * x * (1.f + t) * up[i];
    }
}

// ---------------- SGEMM NN: C[M,N] = A[M,K] @ B[K,N], all %128 / %8 ----------------
__global__ __launch_bounds__(256) void sgemm_nn(
    const float* __restrict__ A, const float* __restrict__ B, float* __restrict__ C,
    int M, int N, int K, int mode) {
    __shared__ float As[8][128];
    __shared__ float Bs[8][128];
    int tid = threadIdx.x;
    int bm = blockIdx.y * 128, bn = blockIdx.x * 128;
    int arow = tid >> 1,  acol = (tid & 1) * 4;
    int brow = tid >> 5,  bcol = (tid & 31) * 4;
    int ty = tid >> 4,    tx = tid & 15;
    float acc[8][8];
    #pragma unroll
    for (int i = 0; i < 8; i++)
        #pragma unroll
        for (int j = 0; j < 8; j++) acc[i][j] = 0.f;
    const float* Ap = A + (size_t)(bm + arow) * K + acol;
    const float* Bp = B + (size_t)brow * N + bn + bcol;
    for (int k0 = 0; k0 < K; k0 += 8) {
        float4 av = *(const float4*)(Ap + k0);
        As[acol+0][arow] = av.x; As[acol+1][arow] = av.y;
        As[acol+2][arow] = av.z; As[acol+3][arow] = av.w;
        *(float4*)(&Bs[brow][bcol]) = *(const float4*)(Bp + (size_t)k0 * N);
        __syncthreads();
        #pragma unroll
        for (int kk = 0; kk < 8; kk++) {
            float a[8], b[8];
            *(float4*)(&a[0]) = *(const float4*)(&As[kk][ty*4]);
            *(float4*)(&a[4]) = *(const float4*)(&As[kk][64 + ty*4]);
            *(float4*)(&b[0]) = *(const float4*)(&Bs[kk][tx*4]);
            *(float4*)(&b[4]) = *(const float4*)(&Bs[kk][64 + tx*4]);
            #pragma unroll
            for (int i = 0; i < 8; i++)
                #pragma unroll
                for (int j = 0; j < 8; j++) acc[i][j] += a[i] * b[j];
        }
        __syncthreads();
    }
    #pragma unroll
    for (int i = 0; i < 8; i++) {
        int row = bm + (i < 4 ? ty*4 + i : 64 + ty*4 + (i-4));
        float* Cr = C + (size_t)row * N + bn;
        float4 v0, v1;
        v0.x = acc[i][0]; v0.y = acc[i][1]; v0.z = acc[i][2]; v0.w = acc[i][3];
        v1.x = acc[i][4]; v1.y = acc[i][5]; v1.z = acc[i][6]; v1.w = acc[i][7];
        if (mode == 1) {
            v0.x = 30.f*tanhf(v0.x/30.f); v0.y = 30.f*tanhf(v0.y/30.f);
            v0.z = 30.f*tanhf(v0.z/30.f); v0.w = 30.f*tanhf(v0.w/30.f);
            v1.x = 30.f*tanhf(v1.x/30.f); v1.y = 30.f*tanhf(v1.y/30.f);
            v1.z = 30.f*tanhf(v1.z/30.f); v1.w = 30.f*tanhf(v1.w/30.f);
        }
        *(float4*)(Cr + tx*4)      = v0;
        *(float4*)(Cr + 64 + tx*4) = v1;
    }
}

// ---------------- attention (no-shift softmax: tanh-cap bounds logits) ----------------
#define QSTR 260
#define ATTN_SMEM_FLOATS (64*QSTR*2 + 64*65 + 64)
__global__ __launch_bounds__(256) void attn_kernel(
    const float* __restrict__ q, const float* __restrict__ k, const float* __restrict__ v,
    float* __restrict__ o, int is_local) {
    extern __shared__ float sm[];
    float* Qs  = sm;
    float* Ks  = Qs + 64*QSTR;
    float* Ps  = Ks + 64*QSTR;
    float* den = Ps + 64*65;
    int tid = threadIdx.x;
    int ty = tid >> 4, tx = tid & 15;
    int t0 = blockIdx.x * 64;
    int n = blockIdx.y, b = blockIdx.z;
    int kvh = n >> 1;

    for (int idx = tid; idx < 64*64; idx += 256) {   // float4 units
        int row = idx >> 6, c4 = idx & 63;
        *(float4*)(&Qs[row*QSTR + c4*4]) =
            *(const float4*)(q + ((size_t)((b*SEQ + t0 + row)*N_HEADS + n))*H_DIM + c4*4);
    }
    if (tid < 64) den[tid] = 0.f;
    float acc[4][16];
    #pragma unroll
    for (int i = 0; i < 4; i++)
        #pragma unroll
        for (int j = 0; j < 16; j++) acc[i][j] = 0.f;

    int s_lo = 0;
    if (is_local) { int lo = t0 - 1023; if (lo > 0) s_lo = lo & ~63; }
    for (int s0 = s_lo; s0 <= t0 + 63; s0 += 64) {
        for (int idx = tid; idx < 64*64; idx += 256) {
            int row = idx >> 6, c4 = idx & 63;
            *(float4*)(&Ks[row*QSTR + c4*4]) =
                *(const float4*)(k + ((size_t)((b*SEQ + s0 + row)*K_HEADS + kvh))*H_DIM + c4*4);
        }
        __syncthreads();
        float s[4][4];
        #pragma unroll
        for (int i = 0; i < 4; i++)
            #pragma unroll
            for (int j = 0; j < 4; j++) s[i][j] = 0.f;
        for (int kk = 0; kk < H_DIM; kk += 4) {
            float4 a[4], bb[4];
            #pragma unroll
            for (int i = 0; i < 4; i++) a[i]  = *(const float4*)(&Qs[(ty*4+i)*QSTR + kk]);
            #pragma unroll
            for (int j = 0; j < 4; j++) bb[j] = *(const float4*)(&Ks[(tx*4+j)*QSTR + kk]);
            #pragma unroll
            for (int i = 0; i < 4; i++)
                #pragma unroll
                for (int j = 0; j < 4; j++)
                    s[i][j] += a[i].x*bb[j].x + a[i].y*bb[j].y + a[i].z*bb[j].z + a[i].w*bb[j].w;
        }
        #pragma unroll
        for (int i = 0; i < 4; i++) {
            int t = t0 + ty*4 + i;
            #pragma unroll
            for (int j = 0; j < 4; j++) {
                int ss = s0 + tx*4 + j;
                float l = 50.f * tanhf(s[i][j] * 0.02f);
                bool ok = (ss <= t) && (!is_local || (t - ss) < 1024);
                Ps[(ty*4+i)*65 + tx*4 + j] = ok ? expf(l) : 0.f;
            }
        }
        __syncthreads();
        if (tid < 64) {
            float d = 0.f;
            #pragma unroll 8
            for (int ss = 0; ss < 64; ss++) d += Ps[tid*65 + ss];
            den[tid] += d;
        }
        for (int idx = tid; idx < 64*64; idx += 256) {
            int row = idx >> 6, c4 = idx & 63;
            *(float4*)(&Ks[row*QSTR + c4*4]) =
                *(const float4*)(v + ((size_t)((b*SEQ + s0 + row)*K_HEADS + kvh))*H_DIM + c4*4);
        }
        __syncthreads();
        for (int ss = 0; ss < 64; ss++) {
            float pr[4];
            #pragma unroll
            for (int i = 0; i < 4; i++) pr[i] = Ps[(ty*4+i)*65 + ss];
            #pragma unroll
            for (int j = 0; j < 16; j++) {
                float vv = Ks[ss*QSTR + j*16 + tx];
                #pragma unroll
                for (int i = 0; i < 4; i++) acc[i][j] += pr[i] * vv;
            }
        }
        __syncthreads();
    }
    #pragma unroll
    for (int i = 0; i < 4; i++) {
        int row = ty*4 + i;
        float inv = 1.f / den[row];
        float* op = o + ((size_t)((b*SEQ + t0 + row)*N_HEADS + n))*H_DIM;
        #pragma unroll
        for (int j = 0; j < 16; j++) op[j*16 + tx] = acc[i][j] * inv;
    }
}

// ---------------- host ----------------
static void* sym(const void* s) { void* p = nullptr; cudaGetSymbolAddress(&p, s); return p; }

extern "C" void kernel_launch(void* const* d_in, const int* in_sizes, int n_in,
                              void* d_out, int out_size) {
    const int*   tokens        = (const int*)  d_in[0];
    const float* embed         = (const float*)d_in[1];
    const float* w_q           = (const float*)d_in[2];
    const float* w_kv          = (const float*)d_in[3];
    const float* w_o           = (const float*)d_in[4];
    const float* attn_norm     = (const float*)d_in[5];
    const float* post_attn     = (const float*)d_in[6];
    const float* ffw_norm      = (const float*)d_in[7];
    const float* post_ffw      = (const float*)d_in[8];
    const float* q_norm        = (const float*)d_in[9];
    const float* k_norm        = (const float*)d_in[10];
    const float* gate_w        = (const float*)d_in[11];
    const float* down_w        = (const float*)d_in[12];
    const float* final_norm    = (const float*)d_in[13];
    float* out = (float*)d_out;

    float* x    = (float*)sym(g_x);
    float* h    = (float*)sym(g_h);
    float* tmpD = (float*)sym(g_tmpD);
    float* qb   = (float*)sym(g_q);
    float* att  = (float*)sym(g_att);
    float* kb   = (float*)sym(g_k);
    float* vb   = (float*)sym(g_v);
    float* gate = (float*)sym(g_gate);
    float* up   = (float*)sym(g_up);
    float* wq   = (float*)sym(g_wq);
    float* wkv  = (float*)sym(g_wkv);
    float* embT = (float*)sym(g_embT);
    float* sint = (float*)sym(g_sin);
    float* cost = (float*)sym(g_cos);

    cudaFuncSetAttribute(attn_kernel, cudaFuncAttributeMaxDynamicSharedMemorySize,
                         ATTN_SMEM_FLOATS * 4);

    // setup
    rope_table_kernel<<<dim3(SEQ, 2), 128>>>(sint, cost);
    {
        size_t tot = (size_t)L_LAYERS * D_MODEL * QCOLS;
        repack_wq_kernel<<<(unsigned)((tot + 255) / 256), 256>>>(w_q, wq);
        tot = (size_t)L_LAYERS * 2 * D_MODEL * KVCOLS;
        repack_wkv_kernel<<<(unsigned)((tot + 255) / 256), 256>>>(w_kv, wkv);
    }
    transpose_kernel<<<dim3(D_MODEL/32, VOCAB/32), dim3(32, 8)>>>(embed, embT, VOCAB, D_MODEL);
    embed_kernel<<<ROWS, 256>>>(tokens, embed, x);

    for (int l = 0; l < L_LAYERS; l++) {
        int is_local = (l % 2 == 0);
        const float* stab = sint + (size_t)(is_local ? 0 : 1) * SEQ * 128;
        const float* ctab = cost + (size_t)(is_local ? 0 : 1) * SEQ * 128;
        // attention block
        rmsnorm_kernel<<<ROWS, 256>>>(x, attn_norm + (size_t)l*D_MODEL, h, D_MODEL);
        sgemm_nn<<<dim3(QCOLS/128,  ROWS/128), 256>>>(h, wq  + (size_t)l*D_MODEL*QCOLS, qb,
                                                      ROWS, QCOLS, D_MODEL, 0);
        sgemm_nn<<<dim3(KVCOLS/128, ROWS/128), 256>>>(h, wkv + (size_t)(l*2+0)*D_MODEL*KVCOLS, kb,
                                                      ROWS, KVCOLS, D_MODEL, 0);
        sgemm_nn<<<dim3(KVCOLS/128, ROWS/128), 256>>>(h, wkv + (size_t)(l*2+1)*D_MODEL*KVCOLS, vb,
                                                      ROWS, KVCOLS, D_MODEL, 0);
        qk_rope_kernel<<<dim3(ROWS, N_HEADS), 128>>>(qb, N_HEADS, q_norm + (size_t)l*H_DIM,
                                                     stab, ctab, 0.0625f);
        qk_rope_kernel<<<dim3(ROWS, K_HEADS), 128>>>(kb, K_HEADS, k_norm + (size_t)l*H_DIM,
                                                     stab, ctab, 1.0f);
        attn_kernel<<<dim3(SEQ/64, N_HEADS, BATCH), 256, ATTN_SMEM_FLOATS*4>>>(
            qb, kb, vb, att, is_local);
        sgemm_nn<<<dim3(D_MODEL/128, ROWS/128), 256>>>(att, w_o + (size_t)l*QCOLS*D_MODEL, tmpD,
                                                       ROWS, D_MODEL, QCOLS, 0);
        add_rmsnorm_kernel<<<ROWS, 256>>>(tmpD, post_attn + (size_t)l*D_MODEL, x, D_MODEL);
        // MLP block
        rmsnorm_kernel<<<ROWS, 256>>>(x, ffw_norm + (size_t)l*D_MODEL, h, D_MODEL);
        sgemm_nn<<<dim3(F_FF/128, ROWS/128), 256>>>(h, gate_w + (size_t)(l*2+0)*D_MODEL*F_FF, gate,
                                                    ROWS, F_FF, D_MODEL, 0);
        sgemm_nn<<<dim3(F_FF/128, ROWS/128), 256>>>(h, gate_w + (size_t)(l*2+1)*D_MODEL*F_FF, up,
                                                    ROWS, F_FF, D_MODEL, 0);
        {
            size_t n = (size_t)ROWS * F_FF;
            geglu_kernel<<<(unsigned)((n + 255) / 256), 256>>>(gate, up, n);
        }
        sgemm_nn<<<dim3(D_MODEL/128, ROWS/128), 256>>>(gate, down_w + (size_t)l*F_FF*D_MODEL, tmpD,
                                                       ROWS, D_MODEL, F_FF, 0);
        add_rmsnorm_kernel<<<ROWS, 256>>>(tmpD, post_ffw + (size_t)l*D_MODEL, x, D_MODEL);
    }
    // final norm + tied decode with tanh cap
    rmsnorm_kernel<<<ROWS, 256>>>(x, final_norm, h, D_MODEL);
    sgemm_nn<<<dim3(VOCAB/128, ROWS/128), 256>>>(h, embT, out, ROWS, VOCAB, D_MODEL, 1);
}